// round 3
// baseline (speedup 1.0000x reference)
#include <cuda_runtime.h>

#define B_   1024
#define C_   128
#define L_   16
#define EQ_  3
#define E_   10
#define P3_  23
#define P2_  5
#define WXV_ 768            // EQ*L*L
#define ROWS_ 12288         // L * WXV

// Scratch: precomputed C3[e][c][i][wxv] = sum_k U3[w,x,v,i,k] * w_max[e,k,c]
__device__ float g_C3[(size_t)E_ * C_ * ROWS_];   // 62.9 MB
__device__ int   g_cnt[E_];
__device__ int   g_nodes[E_ * B_];

__global__ void k_zero() {
    if (threadIdx.x < E_) g_cnt[threadIdx.x] = 0;
}

__global__ void k_classify(const float* __restrict__ y) {
    int b = blockIdx.x * blockDim.x + threadIdx.x;
    if (b >= B_) return;
    int e = 0;
    #pragma unroll
    for (int j = 0; j < E_; j++)
        if (y[b * E_ + j] > 0.5f) e = j;
    int idx = atomicAdd(&g_cnt[e], 1);
    g_nodes[e * B_ + idx] = b;
}

// C3 precompute: GEMM-ish (12288 rows x 23) @ (23 x 128c) per e, tiled with
// smem transpose so global writes are coalesced.
// grid: (192 row-chunks of 64, 4 c-chunks of 32, 10 e), 256 threads.
__global__ __launch_bounds__(256) void k_precompute(
    const float* __restrict__ U3, const float* __restrict__ wmax) {
    __shared__ float u3s[64][24];
    __shared__ float ws[P3_][32];
    __shared__ float outs[32][65];
    int t  = threadIdx.x;
    int rc = blockIdx.x;
    int c0 = blockIdx.y * 32;
    int e  = blockIdx.z;
    int row0 = rc * 64;

    for (int idx = t; idx < 64 * P3_; idx += 256) {
        int rr = idx / P3_, k = idx % P3_;
        int row = row0 + rr;
        int i = row / WXV_;
        int wxv = row - i * WXV_;
        u3s[rr][k] = U3[(wxv * L_ + i) * P3_ + k];
    }
    for (int idx = t; idx < P3_ * 32; idx += 256) {
        int k = idx >> 5, cc = idx & 31;
        ws[k][cc] = wmax[(e * P3_ + k) * C_ + c0 + cc];
    }
    __syncthreads();

    int cc = t & 31, rg = t >> 5;
    #pragma unroll
    for (int rs = 0; rs < 8; rs++) {
        int rr = rg * 8 + rs;
        float acc = 0.f;
        #pragma unroll
        for (int k = 0; k < P3_; k++) acc += u3s[rr][k] * ws[k][cc];
        outs[cc][rr] = acc;
    }
    __syncthreads();

    for (int idx = t; idx < 32 * 64; idx += 256) {
        int c2 = idx >> 6, rr = idx & 63;
        g_C3[(size_t)(e * C_ + c0 + c2) * ROWS_ + row0 + rr] = outs[c2][rr];
    }
}

// Main kernel: one block per (c, e). Thread t owns wxv = {t, t+256, t+512}
// => w = j, xx = t>>4, v = t&15. C3 rows cached in registers.
__global__ __launch_bounds__(256) void k_main(
    const float* __restrict__ x,  const float* __restrict__ U2,
    const float* __restrict__ U1, const float* __restrict__ w2,
    const float* __restrict__ w1, float* __restrict__ out) {
    __shared__ __align__(16) float xs[16][16];
    __shared__ float part[16][3][8];
    __shared__ int   sb[16];

    int t = threadIdx.x;
    int c = blockIdx.x, e = blockIdx.y;
    int nb = g_cnt[e];
    int g = t >> 4, vlane = t & 15;
    int lane = t & 31, wid = t >> 5;

    // Cache this thread's 3 C3 rows (48 floats) in registers. Coalesced LDG.
    const float* base = g_C3 + (size_t)(e * C_ + c) * ROWS_;
    float c3r[3][16];
    #pragma unroll
    for (int i = 0; i < L_; i++)
        #pragma unroll
        for (int j = 0; j < 3; j++)
            c3r[j][i] = base[i * WXV_ + t + j * 256];

    // C2pre[wxv] = sum_k U2[wxv,k] * w2[e,k,c]
    float c2p[3];
    #pragma unroll
    for (int j = 0; j < 3; j++) {
        int wxv = t + j * 256;
        float s = 0.f;
        #pragma unroll
        for (int k = 0; k < P2_; k++)
            s += U2[wxv * P2_ + k] * w2[(e * P2_ + k) * C_ + c];
        c2p[j] = s;
    }
    // C1pre[w, xx=g] = U1[w*16+g] * w1[e,0,c]
    float w1s = w1[e * C_ + c];
    float c1p[3];
    #pragma unroll
    for (int w = 0; w < 3; w++) c1p[w] = U1[w * L_ + g] * w1s;

    for (int jn0 = 0; jn0 < nb; jn0 += 16) {
        __syncthreads();   // protect xs/part/sb reuse
        {   // load 16 node x-vectors cooperatively: thread t -> (slot=g, i=vlane)
            int jn = jn0 + g;
            float xvv = 0.f; int b = -1;
            if (jn < nb) {
                b = g_nodes[e * B_ + jn];
                xvv = x[(b * C_ + c) * L_ + vlane];
            }
            xs[g][vlane] = xvv;
            if (vlane == 0) sb[g] = b;
        }
        __syncthreads();

        #pragma unroll 1
        for (int slot = 0; slot < 16; slot++) {
            const float4* xq = (const float4*)xs[slot];
            float4 q0 = xq[0], q1 = xq[1], q2 = xq[2], q3 = xq[3];
            float a0 = 0.f, a1 = 0.f, a2 = 0.f;
            #define STEP(ii, val) { a0 += c3r[0][ii]*(val); a1 += c3r[1][ii]*(val); a2 += c3r[2][ii]*(val); }
            STEP(0,  q0.x) STEP(1,  q0.y) STEP(2,  q0.z) STEP(3,  q0.w)
            STEP(4,  q1.x) STEP(5,  q1.y) STEP(6,  q1.z) STEP(7,  q1.w)
            STEP(8,  q2.x) STEP(9,  q2.y) STEP(10, q2.z) STEP(11, q2.w)
            STEP(12, q3.x) STEP(13, q3.y) STEP(14, q3.z) STEP(15, q3.w)
            #undef STEP

            float xvv = xs[slot][vlane];
            float xg  = xs[slot][g];
            // stage 2: (out + C2pre) * x[v], reduce over v (16 lanes)
            float v0 = (a0 + c2p[0]) * xvv;
            float v1 = (a1 + c2p[1]) * xvv;
            float v2 = (a2 + c2p[2]) * xvv;
            #pragma unroll
            for (int m = 1; m < 16; m <<= 1) {
                v0 += __shfl_xor_sync(0xffffffffu, v0, m);
                v1 += __shfl_xor_sync(0xffffffffu, v1, m);
                v2 += __shfl_xor_sync(0xffffffffu, v2, m);
            }
            // stage 3: (out2 + C1pre) * x[xx=g], reduce over g
            v0 = (v0 + c1p[0]) * xg;
            v1 = (v1 + c1p[1]) * xg;
            v2 = (v2 + c1p[2]) * xg;
            v0 += __shfl_xor_sync(0xffffffffu, v0, 16);
            v1 += __shfl_xor_sync(0xffffffffu, v1, 16);
            v2 += __shfl_xor_sync(0xffffffffu, v2, 16);
            if (lane == 0) {
                part[slot][0][wid] = v0;
                part[slot][1][wid] = v1;
                part[slot][2][wid] = v2;
            }
        }
        __syncthreads();

        // finish: sum 8 warp-partials per (slot, w), write output
        if (t < 48) {
            int slot = t / 3, w = t - slot * 3;
            int b = sb[slot];
            if (b >= 0) {
                float s = 0.f;
                #pragma unroll
                for (int ww = 0; ww < 8; ww++) s += part[slot][w][ww];
                out[b * (C_ * EQ_) + c * EQ_ + w] = s;
            }
        }
    }
}

extern "C" void kernel_launch(void* const* d_in, const int* in_sizes, int n_in,
                              void* d_out, int out_size) {
    const float* x    = (const float*)d_in[0];
    const float* y    = (const float*)d_in[1];
    const float* U3   = (const float*)d_in[2];
    const float* U2   = (const float*)d_in[3];
    const float* U1   = (const float*)d_in[4];
    const float* wmax = (const float*)d_in[5];
    const float* w2   = (const float*)d_in[6];
    const float* w1   = (const float*)d_in[7];
    float* out = (float*)d_out;

    k_zero<<<1, 32>>>();
    k_classify<<<4, 256>>>(y);
    k_precompute<<<dim3(192, 4, 10), 256>>>(U3, wmax);
    k_main<<<dim3(C_, E_), 256>>>(x, U2, U1, w2, w1, out);
}